// round 8
// baseline (speedup 1.0000x reference)
#include <cuda_runtime.h>
#include <cuda_bf16.h>
#include <math.h>
#include <stdint.h>

#define BB      4
#define NN      1024
#define HH      1024
#define NHEADS  16
#define DD      64
#define ROWS    (BB*NN)      // 4096
#define BH      (BB*NHEADS)  // 64

// ---------------- tensor-core helpers ----------------
__device__ __forceinline__ void mma16816(float* c, const uint32_t* a, const uint32_t* b) {
    asm volatile("mma.sync.aligned.m16n8k16.row.col.f32.bf16.bf16.f32 "
        "{%0,%1,%2,%3},{%4,%5,%6,%7},{%8,%9},{%0,%1,%2,%3};"
        : "+f"(c[0]), "+f"(c[1]), "+f"(c[2]), "+f"(c[3])
        : "r"(a[0]), "r"(a[1]), "r"(a[2]), "r"(a[3]), "r"(b[0]), "r"(b[1]));
}
__device__ __forceinline__ void ldsm4(uint32_t* r, const void* p) {
    uint32_t addr = (uint32_t)__cvta_generic_to_shared(p);
    asm volatile("ldmatrix.sync.aligned.m8n8.x4.shared.b16 {%0,%1,%2,%3},[%4];"
        : "=r"(r[0]), "=r"(r[1]), "=r"(r[2]), "=r"(r[3]) : "r"(addr));
}
// split (a,b) into bf16 hi/lo packed words
__device__ __forceinline__ void split2(float a, float b, uint32_t& hw, uint32_t& lw) {
    __nv_bfloat162 hp = __float22bfloat162_rn(make_float2(a, b));
    float ra = a - __bfloat162float(hp.x);
    float rb = b - __bfloat162float(hp.y);
    __nv_bfloat162 lp = __float22bfloat162_rn(make_float2(ra, rb));
    hw = *(uint32_t*)&hp; lw = *(uint32_t*)&lp;
}

// ---------------- scratch (__device__ globals) ----------------
__device__ __nv_bfloat16 g_xhi[(size_t)ROWS*HH], g_xlo[(size_t)ROWS*HH];
__device__ __nv_bfloat16 g_whi[(size_t)3*HH*HH], g_wlo[(size_t)3*HH*HH];
__device__ __nv_bfloat16 g_qhi[(size_t)BH*NN*DD], g_qlo[(size_t)BH*NN*DD];
__device__ __nv_bfloat16 g_khi[(size_t)BH*NN*DD], g_klo[(size_t)BH*NN*DD];
__device__ __nv_bfloat16 g_vthi[(size_t)BH*DD*NN], g_vtlo[(size_t)BH*DD*NN]; // (z,d,n)
__device__ float g_rowmax[BH*NN];
__device__ float g_rowsum[BH*NN];
__device__ int   g_padd[BB];

// ---------------------------------------------------------------------------
// K0: padd[b]
// ---------------------------------------------------------------------------
__global__ void k_padd(const int* __restrict__ pad) {
    int b = blockIdx.x;
    __shared__ int sh[256];
    int t = threadIdx.x;
    int s = 0;
    for (int i = t; i < NN; i += 256) s += pad[b*NN + i];
    sh[t] = s; __syncthreads();
    for (int o = 128; o > 0; o >>= 1) { if (t < o) sh[t] += sh[t+o]; __syncthreads(); }
    if (t == 0) g_padd[b] = sh[0];
}

// ---------------------------------------------------------------------------
// K-conv: fp32 -> bf16 hi/lo (count must be multiple of 4*blockDim*grid stride)
// ---------------------------------------------------------------------------
__global__ void k_conv(const float* __restrict__ src,
                       __nv_bfloat16* __restrict__ hi,
                       __nv_bfloat16* __restrict__ lo) {
    size_t i = (size_t)blockIdx.x * blockDim.x + threadIdx.x;
    float4 v = ((const float4*)src)[i];
    uint2 hw, lw;
    split2(v.x, v.y, hw.x, lw.x);
    split2(v.z, v.w, hw.y, lw.y);
    ((uint2*)hi)[i] = hw;
    ((uint2*)lo)[i] = lw;
}

// ---------------------------------------------------------------------------
// K1: QKV projection, pure bf16 GEMM (3-product split), 128x128 tile.
//     z=0: q (fp32 out + hi/lo), z=1: k (fp32 out + hi/lo), z=2: v (V^T hi/lo).
// ---------------------------------------------------------------------------
__global__ __launch_bounds__(256) void k_qkv(
        const float* __restrict__ bq, const float* __restrict__ bk,
        const float* __restrict__ bv,
        float* __restrict__ outq, float* __restrict__ outk) {
    __shared__ __align__(16) __nv_bfloat16 sAhi[128][40], sAlo[128][40];
    __shared__ __align__(16) __nv_bfloat16 sBhi[128][40], sBlo[128][40];

    int z = blockIdx.z;
    const __nv_bfloat16* Whi = g_whi + (size_t)z*HH*HH;
    const __nv_bfloat16* Wlo = g_wlo + (size_t)z*HH*HH;
    const float* bias = (z == 0) ? bq : (z == 1) ? bk : bv;

    int tid = threadIdx.x, lane = tid & 31, w = tid >> 5;
    int wm = w & 3, wn = w >> 2;
    int r0 = blockIdx.y * 128, o0 = blockIdx.x * 128;

    int lrow = tid >> 2, lseg = (tid & 3) * 8;   // 64 rows per pass, 8-col segs

    float acc[2][8][4];
    #pragma unroll
    for (int i = 0; i < 2; i++)
        #pragma unroll
        for (int j = 0; j < 8; j++)
            #pragma unroll
            for (int c = 0; c < 4; c++) acc[i][j][c] = 0.f;

    int arow = wm*32 + (lane & 15);
    int brow = wn*64 + (lane & 7) + ((lane >> 4) << 3);
    int bcol8 = ((lane >> 3) & 1) * 8;
    int acol8 = (lane >> 4) * 8;

    for (int kt = 0; kt < HH; kt += 32) {
        uint4 ax[2], al[2], bx[2], bl[2];
        #pragma unroll
        for (int hf = 0; hf < 2; hf++) {
            size_t ai = (size_t)(r0 + lrow + hf*64)*HH + kt + lseg;
            size_t bi = (size_t)(o0 + lrow + hf*64)*HH + kt + lseg;
            ax[hf] = *(const uint4*)&g_xhi[ai];
            al[hf] = *(const uint4*)&g_xlo[ai];
            bx[hf] = *(const uint4*)&Whi[bi];
            bl[hf] = *(const uint4*)&Wlo[bi];
        }
        __syncthreads();
        #pragma unroll
        for (int hf = 0; hf < 2; hf++) {
            *(uint4*)&sAhi[lrow + hf*64][lseg] = ax[hf];
            *(uint4*)&sAlo[lrow + hf*64][lseg] = al[hf];
            *(uint4*)&sBhi[lrow + hf*64][lseg] = bx[hf];
            *(uint4*)&sBlo[lrow + hf*64][lseg] = bl[hf];
        }
        __syncthreads();

        #pragma unroll
        for (int k16 = 0; k16 < 32; k16 += 16) {
            uint32_t ahi[2][4], alo2[2][4];
            #pragma unroll
            for (int mt = 0; mt < 2; mt++) {
                ldsm4(ahi[mt],  &sAhi[arow + mt*16][k16 + acol8]);
                ldsm4(alo2[mt], &sAlo[arow + mt*16][k16 + acol8]);
            }
            #pragma unroll
            for (int p = 0; p < 4; p++) {
                uint32_t bh[4], blw[4];
                ldsm4(bh,  &sBhi[brow + p*16][k16 + bcol8]);
                ldsm4(blw, &sBlo[brow + p*16][k16 + bcol8]);
                #pragma unroll
                for (int mt = 0; mt < 2; mt++) {
                    mma16816(acc[mt][2*p],   ahi[mt],  bh);
                    mma16816(acc[mt][2*p],   ahi[mt],  blw);
                    mma16816(acc[mt][2*p],   alo2[mt], bh);
                    mma16816(acc[mt][2*p+1], ahi[mt],  bh+2);
                    mma16816(acc[mt][2*p+1], ahi[mt],  blw+2);
                    mma16816(acc[mt][2*p+1], alo2[mt], bh+2);
                }
            }
        }
    }

    // epilogue
    int g = lane >> 2, t2 = (lane & 3) * 2;
    __nv_bfloat16* ghi = (z == 0) ? g_qhi : g_khi;
    __nv_bfloat16* glo = (z == 0) ? g_qlo : g_klo;
    float* outf = (z == 0) ? outq : outk;
    #pragma unroll
    for (int nt = 0; nt < 8; nt++) {
        int colg = o0 + wn*64 + nt*8 + t2;
        float b0v = bias[colg], b1v = bias[colg+1];
        int h = colg >> 6, dd = colg & 63;
        #pragma unroll
        for (int mt = 0; mt < 2; mt++) {
            #pragma unroll
            for (int half = 0; half < 2; half++) {
                int r = r0 + wm*32 + mt*16 + g + half*8;
                int b_ = r >> 10, n = r & 1023;
                float v0 = acc[mt][nt][2*half]   + b0v;
                float v1 = acc[mt][nt][2*half+1] + b1v;
                int zz = b_*NHEADS + h;
                if (z < 2) {
                    size_t base = (((size_t)zz)*NN + n)*DD + dd;
                    *(float2*)(outf + base) = make_float2(v0, v1);
                    uint32_t hw, lw;
                    split2(v0, v1, hw, lw);
                    *(uint32_t*)(ghi + base) = hw;
                    *(uint32_t*)(glo + base) = lw;
                } else {
                    // V^T layout (z, d, n)
                    uint32_t hw, lw;
                    split2(v0, v1, hw, lw);
                    __nv_bfloat162 hp = *(__nv_bfloat162*)&hw;
                    __nv_bfloat162 lp = *(__nv_bfloat162*)&lw;
                    size_t b0i = ((size_t)zz*DD + dd)*NN + n;
                    size_t b1i = ((size_t)zz*DD + dd + 1)*NN + n;
                    g_vthi[b0i] = hp.x; g_vtlo[b0i] = lp.x;
                    g_vthi[b1i] = hp.y; g_vtlo[b1i] = lp.y;
                }
            }
        }
    }
}

// ---------------------------------------------------------------------------
// K2: scores = Q K^T / 8, K=64 resident, pure bf16 mma.
// ---------------------------------------------------------------------------
__global__ __launch_bounds__(256) void k_scores(float* __restrict__ scores) {
    extern __shared__ __nv_bfloat16 sm2[];
    __nv_bfloat16 (*Qhi)[72] = (__nv_bfloat16(*)[72])sm2;
    __nv_bfloat16 (*Qlo)[72] = Qhi + 128;
    __nv_bfloat16 (*Khi)[72] = Qlo + 128;
    __nv_bfloat16 (*Klo)[72] = Khi + 128;

    int z = blockIdx.z;
    float* S = scores + (size_t)z*NN*NN;
    int tid = threadIdx.x, lane = tid & 31, w = tid >> 5;
    int wm = w & 3, wn = w >> 2;
    int n0 = blockIdx.y * 128, m0 = blockIdx.x * 128;

    // load Q/K tiles (K=64): thread -> row tid>>1, 4 uint4 at (tid&1)*32
    {
        int lr = tid >> 1, c0 = (tid & 1) * 32;
        size_t qi = ((size_t)z*NN + n0 + lr)*DD + c0;
        size_t ki = ((size_t)z*NN + m0 + lr)*DD + c0;
        #pragma unroll
        for (int c = 0; c < 4; c++) {
            *(uint4*)&Qhi[lr][c0 + c*8] = *(const uint4*)&g_qhi[qi + c*8];
            *(uint4*)&Qlo[lr][c0 + c*8] = *(const uint4*)&g_qlo[qi + c*8];
            *(uint4*)&Khi[lr][c0 + c*8] = *(const uint4*)&g_khi[ki + c*8];
            *(uint4*)&Klo[lr][c0 + c*8] = *(const uint4*)&g_klo[ki + c*8];
        }
    }
    __syncthreads();

    float acc[2][8][4];
    #pragma unroll
    for (int i = 0; i < 2; i++)
        #pragma unroll
        for (int j = 0; j < 8; j++)
            #pragma unroll
            for (int c = 0; c < 4; c++) acc[i][j][c] = 0.f;

    int arow = wm*32 + (lane & 15);
    int brow = wn*64 + (lane & 7) + ((lane >> 4) << 3);
    int bcol8 = ((lane >> 3) & 1) * 8;
    int acol8 = (lane >> 4) * 8;

    #pragma unroll
    for (int k16 = 0; k16 < DD; k16 += 16) {
        uint32_t ahi[2][4], alo2[2][4];
        #pragma unroll
        for (int mt = 0; mt < 2; mt++) {
            ldsm4(ahi[mt],  &Qhi[arow + mt*16][k16 + acol8]);
            ldsm4(alo2[mt], &Qlo[arow + mt*16][k16 + acol8]);
        }
        #pragma unroll
        for (int p = 0; p < 4; p++) {
            uint32_t bh[4], blw[4];
            ldsm4(bh,  &Khi[brow + p*16][k16 + bcol8]);
            ldsm4(blw, &Klo[brow + p*16][k16 + bcol8]);
            #pragma unroll
            for (int mt = 0; mt < 2; mt++) {
                mma16816(acc[mt][2*p],   ahi[mt],  bh);
                mma16816(acc[mt][2*p],   ahi[mt],  blw);
                mma16816(acc[mt][2*p],   alo2[mt], bh);
                mma16816(acc[mt][2*p+1], ahi[mt],  bh+2);
                mma16816(acc[mt][2*p+1], ahi[mt],  blw+2);
                mma16816(acc[mt][2*p+1], alo2[mt], bh+2);
            }
        }
    }

    int g = lane >> 2, t2 = (lane & 3) * 2;
    #pragma unroll
    for (int mt = 0; mt < 2; mt++) {
        int r = n0 + wm*32 + mt*16 + g;
        #pragma unroll
        for (int nt = 0; nt < 8; nt++) {
            int col = m0 + wn*64 + nt*8 + t2;
            *(float2*)(S + (size_t)r*NN + col) =
                make_float2(acc[mt][nt][0]*0.125f, acc[mt][nt][1]*0.125f);
            *(float2*)(S + (size_t)(r+8)*NN + col) =
                make_float2(acc[mt][nt][2]*0.125f, acc[mt][nt][3]*0.125f);
        }
    }
}

// ---------------------------------------------------------------------------
// K3: per-row softmax stats
// ---------------------------------------------------------------------------
__global__ void k_stats(const float* __restrict__ scores) {
    int gwarp = (blockIdx.x * blockDim.x + threadIdx.x) >> 5;
    int lane  = threadIdx.x & 31;
    if (gwarp >= BH*NN) return;
    int b = gwarp / (NHEADS*NN);
    int n = gwarp & (NN-1);
    int padd = g_padd[b];
    if (n >= padd) {
        if (lane == 0) { g_rowmax[gwarp] = 0.f; g_rowsum[gwarp] = 1.f; }
        return;
    }
    const float* row = scores + (size_t)gwarp*NN;
    float vmax = -1e30f, vsum = 0.f;
    for (int m4 = lane*4; m4 < NN; m4 += 128) {
        if (m4 >= padd) break;
        float4 s4 = *(const float4*)(row + m4);
        float sv[4] = {s4.x, s4.y, s4.z, s4.w};
        #pragma unroll
        for (int j = 0; j < 4; j++) {
            if (m4 + j >= padd) break;
            float s = sv[j];
            if (s > vmax) { vsum = vsum*__expf(vmax - s) + 1.f; vmax = s; }
            else            vsum += __expf(s - vmax);
        }
    }
    #pragma unroll
    for (int o = 16; o > 0; o >>= 1) {
        float omax = __shfl_xor_sync(0xffffffffu, vmax, o);
        float osum = __shfl_xor_sync(0xffffffffu, vsum, o);
        float m2 = fmaxf(vmax, omax);
        vsum = vsum*__expf(vmax - m2) + osum*__expf(omax - m2);
        vmax = m2;
    }
    if (lane == 0) { g_rowmax[gwarp] = vmax; g_rowsum[gwarp] = vsum; }
}

// ---------------------------------------------------------------------------
// K4: zero attention_values
// ---------------------------------------------------------------------------
__global__ void k_zero(float* __restrict__ av) {
    av[(size_t)blockIdx.x*1024 + threadIdx.x] = 0.f;
}

// ---------------------------------------------------------------------------
// K5: context = P @ V (tensor cores, bf16 hi/lo 3-product) + column sums.
// ---------------------------------------------------------------------------
__global__ __launch_bounds__(256) void k_ctx(const float* __restrict__ scores,
        float* __restrict__ ctx, float* __restrict__ av) {
    extern __shared__ __nv_bfloat16 smc[];
    __nv_bfloat16 (*Phi)[136] = (__nv_bfloat16(*)[136])smc;          // [n][m]
    __nv_bfloat16 (*Plo)[136] = Phi + 128;
    __nv_bfloat16 (*Vhi)[136] = Plo + 128;                           // [d][m]
    __nv_bfloat16 (*Vlo)[136] = Vhi + 64;
    float* smax = (float*)(Vlo + 64);
    float* sinv = smax + 128;

    int z = blockIdx.y, b = z >> 4;
    int padd = g_padd[b];
    int n0 = blockIdx.x * 128;
    int tid = threadIdx.x, lane = tid & 31, w = tid >> 5;
    int wm = w & 3, wn = w >> 2;

    if (n0 >= padd) {
        float4 zz = make_float4(0.f,0.f,0.f,0.f);
        for (int e = 0; e < 8; e++) {
            int l = e*256 + tid;
            *(float4*)(ctx + ((size_t)z*NN + n0)*DD + l*4) = zz;
        }
        return;
    }

    const float* S = scores + (size_t)z*NN*NN;

    if (tid < 128) {
        int row = z*NN + n0 + tid;
        smax[tid] = g_rowmax[row];
        sinv[tid] = 1.f / g_rowsum[row];
    }
    __syncthreads();

    float acc[2][4][4];
    #pragma unroll
    for (int i = 0; i < 2; i++)
        #pragma unroll
        for (int j = 0; j < 4; j++)
            #pragma unroll
            for (int c = 0; c < 4; c++) acc[i][j][c] = 0.f;

    int arow = wm*32 + (lane & 15);
    int brow = wn*32 + (lane & 7) + ((lane >> 4) << 3);
    int bcol8 = ((lane >> 3) & 1) * 8;
    int acol8 = (lane >> 4) * 8;

    for (int m0 = 0; m0 < padd; m0 += 128) {
        // build P tile -> bf16 hi/lo
        #pragma unroll
        for (int e = 0; e < 16; e++) {
            int l = e*256 + tid;
            int n = l >> 5, m4 = (l & 31) * 4;
            float4 s4 = *(const float4*)(S + (size_t)(n0+n)*NN + m0 + m4);
            float4 p4 = make_float4(0.f, 0.f, 0.f, 0.f);
            if (n0 + n < padd) {
                float mx = smax[n], iv = sinv[n];
                int mg = m0 + m4;
                if (mg + 0 < padd) p4.x = __expf(s4.x - mx) * iv;
                if (mg + 1 < padd) p4.y = __expf(s4.y - mx) * iv;
                if (mg + 2 < padd) p4.z = __expf(s4.z - mx) * iv;
                if (mg + 3 < padd) p4.w = __expf(s4.w - mx) * iv;
            }
            uint2 hw, lw;
            split2(p4.x, p4.y, hw.x, lw.x);
            split2(p4.z, p4.w, hw.y, lw.y);
            *(uint2*)&Phi[n][m4] = hw;
            *(uint2*)&Plo[n][m4] = lw;
        }
        // load V^T tiles: rows d (64), cols m (128)
        {
            int dr = tid >> 2;                  // 0..63
            int c0 = (tid & 3) * 8;             // 4 segs of 8, stride 32
            size_t vi = ((size_t)z*DD + dr)*NN + m0 + c0;
            #pragma unroll
            for (int c = 0; c < 4; c++) {
                *(uint4*)&Vhi[dr][c0 + c*32] = *(const uint4*)&g_vthi[vi + c*32];
                *(uint4*)&Vlo[dr][c0 + c*32] = *(const uint4*)&g_vtlo[vi + c*32];
            }
        }
        __syncthreads();

        // mma: acc[n][d] += P[n][m] * V^T[d][m]
        #pragma unroll
        for (int k16 = 0; k16 < 128; k16 += 16) {
            uint32_t ahi[2][4], alo2[2][4];
            #pragma unroll
            for (int mt = 0; mt < 2; mt++) {
                ldsm4(ahi[mt],  &Phi[arow + mt*16][k16 + acol8]);
                ldsm4(alo2[mt], &Plo[arow + mt*16][k16 + acol8]);
            }
            #pragma unroll
            for (int p = 0; p < 2; p++) {
                uint32_t bh[4], blw[4];
                ldsm4(bh,  &Vhi[brow + p*16][k16 + bcol8]);
                ldsm4(blw, &Vlo[brow + p*16][k16 + bcol8]);
                #pragma unroll
                for (int mt = 0; mt < 2; mt++) {
                    mma16816(acc[mt][2*p],   ahi[mt],  bh);
                    mma16816(acc[mt][2*p],   ahi[mt],  blw);
                    mma16816(acc[mt][2*p],   alo2[mt], bh);
                    mma16816(acc[mt][2*p+1], ahi[mt],  bh+2);
                    mma16816(acc[mt][2*p+1], ahi[mt],  blw+2);
                    mma16816(acc[mt][2*p+1], alo2[mt], bh+2);
                }
            }
        }

        // column sums -> attention_values (exact: hi+lo)
        if (tid < 128) {
            float s = 0.f;
            #pragma unroll 4
            for (int n = 0; n < 128; n++)
                s += __bfloat162float(Phi[n][tid]) + __bfloat162float(Plo[n][tid]);
            if (s != 0.f) atomicAdd(av + (size_t)z*NN + m0 + tid, s);
        }
        __syncthreads();
    }

    int g = lane >> 2, t2 = (lane & 3) * 2;
    #pragma unroll
    for (int mt = 0; mt < 2; mt++) {
        #pragma unroll
        for (int nt = 0; nt < 4; nt++) {
            int col = wn*32 + nt*8 + t2;
            int r = n0 + wm*32 + mt*16 + g;
            *(float2*)(ctx + ((size_t)z*NN + r)*DD + col) =
                make_float2(acc[mt][nt][0], acc[mt][nt][1]);
            *(float2*)(ctx + ((size_t)z*NN + r + 8)*DD + col) =
                make_float2(acc[mt][nt][2], acc[mt][nt][3]);
        }
    }
}

// ---------------------------------------------------------------------------
extern "C" void kernel_launch(void* const* d_in, const int* in_sizes, int n_in,
                              void* d_out, int out_size) {
    const float* hs = (const float*)d_in[0];
    const int*  pad = (const int*)  d_in[1];
    const float* Wq = (const float*)d_in[2];
    const float* bq = (const float*)d_in[3];
    const float* Wk = (const float*)d_in[4];
    const float* bk = (const float*)d_in[5];
    const float* Wv = (const float*)d_in[6];
    const float* bv = (const float*)d_in[7];

    float* out    = (float*)d_out;
    float* av     = out;
    float* outk   = av + (size_t)BH*NN;
    float* outq   = outk + (size_t)BH*NN*DD;
    float* ctx    = outq + (size_t)BH*NN*DD;
    float* scores = ctx  + (size_t)BH*NN*DD;

    // resolve scratch symbol addresses (host-side, not stream ops)
    static __nv_bfloat16 *xhi=nullptr,*xlo=nullptr,*whi=nullptr,*wlo=nullptr;
    if (!xhi) {
        cudaGetSymbolAddress((void**)&xhi, g_xhi);
        cudaGetSymbolAddress((void**)&xlo, g_xlo);
        cudaGetSymbolAddress((void**)&whi, g_whi);
        cudaGetSymbolAddress((void**)&wlo, g_wlo);
    }

    const int SC_SMEM  = 4*128*72*2;                          // 73728
    const int CTX_SMEM = (2*128*136 + 2*64*136)*2 + 256*4;    // 105472
    cudaFuncSetAttribute(k_scores, cudaFuncAttributeMaxDynamicSharedMemorySize, SC_SMEM);
    cudaFuncSetAttribute(k_ctx,    cudaFuncAttributeMaxDynamicSharedMemorySize, CTX_SMEM);

    k_padd  <<<BB, 256>>>(pad);
    k_conv  <<<(ROWS*HH/4)/256, 256>>>(hs, xhi, xlo);
    k_conv  <<<(HH*HH/4)/256, 256>>>(Wq, whi,            wlo);
    k_conv  <<<(HH*HH/4)/256, 256>>>(Wk, whi + HH*HH,    wlo + HH*HH);
    k_conv  <<<(HH*HH/4)/256, 256>>>(Wv, whi + 2*HH*HH,  wlo + 2*HH*HH);
    k_qkv   <<<dim3(HH/128, ROWS/128, 3), 256>>>(bq, bk, bv, outq, outk);
    k_scores<<<dim3(NN/128, NN/128, BH), 256, SC_SMEM>>>(scores);
    k_stats <<<(BH*NN*32)/256, 256>>>(scores);
    k_zero  <<<BH, 1024>>>(av);
    k_ctx   <<<dim3(NN/128, BH), 256, CTX_SMEM>>>(scores, ctx, av);
}

// round 9
// speedup vs baseline: 1.0095x; 1.0095x over previous
#include <cuda_runtime.h>
#include <cuda_bf16.h>
#include <math.h>
#include <stdint.h>

#define BB      4
#define NN      1024
#define HH      1024
#define NHEADS  16
#define DD      64
#define ROWS    (BB*NN)      // 4096
#define BH      (BB*NHEADS)  // 64

// ---------------- tensor-core helpers ----------------
__device__ __forceinline__ void mma16816(float* c, const uint32_t* a, const uint32_t* b) {
    asm volatile("mma.sync.aligned.m16n8k16.row.col.f32.bf16.bf16.f32 "
        "{%0,%1,%2,%3},{%4,%5,%6,%7},{%8,%9},{%0,%1,%2,%3};"
        : "+f"(c[0]), "+f"(c[1]), "+f"(c[2]), "+f"(c[3])
        : "r"(a[0]), "r"(a[1]), "r"(a[2]), "r"(a[3]), "r"(b[0]), "r"(b[1]));
}
__device__ __forceinline__ void ldsm4(uint32_t* r, const void* p) {
    uint32_t addr = (uint32_t)__cvta_generic_to_shared(p);
    asm volatile("ldmatrix.sync.aligned.m8n8.x4.shared.b16 {%0,%1,%2,%3},[%4];"
        : "=r"(r[0]), "=r"(r[1]), "=r"(r[2]), "=r"(r[3]) : "r"(addr));
}
// split (a,b) into bf16 hi/lo packed words
__device__ __forceinline__ void split2(float a, float b, uint32_t& hw, uint32_t& lw) {
    __nv_bfloat162 hp = __float22bfloat162_rn(make_float2(a, b));
    float ra = a - __bfloat162float(hp.x);
    float rb = b - __bfloat162float(hp.y);
    __nv_bfloat162 lp = __float22bfloat162_rn(make_float2(ra, rb));
    hw = *(uint32_t*)&hp; lw = *(uint32_t*)&lp;
}

// ---------------- scratch (__device__ globals) ----------------
__device__ __nv_bfloat16 g_xhi[(size_t)ROWS*HH], g_xlo[(size_t)ROWS*HH];
__device__ __nv_bfloat16 g_whi[(size_t)3*HH*HH], g_wlo[(size_t)3*HH*HH];
__device__ __nv_bfloat16 g_qhi[(size_t)BH*NN*DD], g_qlo[(size_t)BH*NN*DD];
__device__ __nv_bfloat16 g_khi[(size_t)BH*NN*DD], g_klo[(size_t)BH*NN*DD];
__device__ __nv_bfloat16 g_vthi[(size_t)BH*DD*NN], g_vtlo[(size_t)BH*DD*NN]; // (z,d,n)
__device__ float g_rowmax[BH*NN];
__device__ float g_rowsum[BH*NN];
__device__ int   g_padd[BB];

// ---------------------------------------------------------------------------
// K0: padd[b]
// ---------------------------------------------------------------------------
__global__ void k_padd(const int* __restrict__ pad) {
    int b = blockIdx.x;
    __shared__ int sh[256];
    int t = threadIdx.x;
    int s = 0;
    for (int i = t; i < NN; i += 256) s += pad[b*NN + i];
    sh[t] = s; __syncthreads();
    for (int o = 128; o > 0; o >>= 1) { if (t < o) sh[t] += sh[t+o]; __syncthreads(); }
    if (t == 0) g_padd[b] = sh[0];
}

// ---------------------------------------------------------------------------
// K-conv: fp32 -> bf16 hi/lo (count must be multiple of 4*blockDim*grid stride)
// ---------------------------------------------------------------------------
__global__ void k_conv(const float* __restrict__ src,
                       __nv_bfloat16* __restrict__ hi,
                       __nv_bfloat16* __restrict__ lo) {
    size_t i = (size_t)blockIdx.x * blockDim.x + threadIdx.x;
    float4 v = ((const float4*)src)[i];
    uint2 hw, lw;
    split2(v.x, v.y, hw.x, lw.x);
    split2(v.z, v.w, hw.y, lw.y);
    ((uint2*)hi)[i] = hw;
    ((uint2*)lo)[i] = lw;
}

// ---------------------------------------------------------------------------
// K1: QKV projection, pure bf16 GEMM (3-product split), 128x128 tile.
//     z=0: q (fp32 out + hi/lo), z=1: k (fp32 out + hi/lo), z=2: v (V^T hi/lo).
// ---------------------------------------------------------------------------
__global__ __launch_bounds__(256) void k_qkv(
        const float* __restrict__ bq, const float* __restrict__ bk,
        const float* __restrict__ bv,
        float* __restrict__ outq, float* __restrict__ outk) {
    __shared__ __align__(16) __nv_bfloat16 sAhi[128][40], sAlo[128][40];
    __shared__ __align__(16) __nv_bfloat16 sBhi[128][40], sBlo[128][40];

    int z = blockIdx.z;
    const __nv_bfloat16* Whi = g_whi + (size_t)z*HH*HH;
    const __nv_bfloat16* Wlo = g_wlo + (size_t)z*HH*HH;
    const float* bias = (z == 0) ? bq : (z == 1) ? bk : bv;

    int tid = threadIdx.x, lane = tid & 31, w = tid >> 5;
    int wm = w & 3, wn = w >> 2;
    int r0 = blockIdx.y * 128, o0 = blockIdx.x * 128;

    int lrow = tid >> 2, lseg = (tid & 3) * 8;   // 64 rows per pass, 8-col segs

    float acc[2][8][4];
    #pragma unroll
    for (int i = 0; i < 2; i++)
        #pragma unroll
        for (int j = 0; j < 8; j++)
            #pragma unroll
            for (int c = 0; c < 4; c++) acc[i][j][c] = 0.f;

    int arow = wm*32 + (lane & 15);
    int brow = wn*64 + (lane & 7) + ((lane >> 4) << 3);
    int bcol8 = ((lane >> 3) & 1) * 8;
    int acol8 = (lane >> 4) * 8;

    for (int kt = 0; kt < HH; kt += 32) {
        uint4 ax[2], al[2], bx[2], bl[2];
        #pragma unroll
        for (int hf = 0; hf < 2; hf++) {
            size_t ai = (size_t)(r0 + lrow + hf*64)*HH + kt + lseg;
            size_t bi = (size_t)(o0 + lrow + hf*64)*HH + kt + lseg;
            ax[hf] = *(const uint4*)&g_xhi[ai];
            al[hf] = *(const uint4*)&g_xlo[ai];
            bx[hf] = *(const uint4*)&Whi[bi];
            bl[hf] = *(const uint4*)&Wlo[bi];
        }
        __syncthreads();
        #pragma unroll
        for (int hf = 0; hf < 2; hf++) {
            *(uint4*)&sAhi[lrow + hf*64][lseg] = ax[hf];
            *(uint4*)&sAlo[lrow + hf*64][lseg] = al[hf];
            *(uint4*)&sBhi[lrow + hf*64][lseg] = bx[hf];
            *(uint4*)&sBlo[lrow + hf*64][lseg] = bl[hf];
        }
        __syncthreads();

        #pragma unroll
        for (int k16 = 0; k16 < 32; k16 += 16) {
            uint32_t ahi[2][4], alo2[2][4];
            #pragma unroll
            for (int mt = 0; mt < 2; mt++) {
                ldsm4(ahi[mt],  &sAhi[arow + mt*16][k16 + acol8]);
                ldsm4(alo2[mt], &sAlo[arow + mt*16][k16 + acol8]);
            }
            #pragma unroll
            for (int p = 0; p < 4; p++) {
                uint32_t bh[4], blw[4];
                ldsm4(bh,  &sBhi[brow + p*16][k16 + bcol8]);
                ldsm4(blw, &sBlo[brow + p*16][k16 + bcol8]);
                #pragma unroll
                for (int mt = 0; mt < 2; mt++) {
                    mma16816(acc[mt][2*p],   ahi[mt],  bh);
                    mma16816(acc[mt][2*p],   ahi[mt],  blw);
                    mma16816(acc[mt][2*p],   alo2[mt], bh);
                    mma16816(acc[mt][2*p+1], ahi[mt],  bh+2);
                    mma16816(acc[mt][2*p+1], ahi[mt],  blw+2);
                    mma16816(acc[mt][2*p+1], alo2[mt], bh+2);
                }
            }
        }
    }

    // epilogue
    int g = lane >> 2, t2 = (lane & 3) * 2;
    __nv_bfloat16* ghi = (z == 0) ? g_qhi : g_khi;
    __nv_bfloat16* glo = (z == 0) ? g_qlo : g_klo;
    float* outf = (z == 0) ? outq : outk;
    #pragma unroll
    for (int nt = 0; nt < 8; nt++) {
        int colg = o0 + wn*64 + nt*8 + t2;
        float b0v = bias[colg], b1v = bias[colg+1];
        int h = colg >> 6, dd = colg & 63;
        #pragma unroll
        for (int mt = 0; mt < 2; mt++) {
            #pragma unroll
            for (int half = 0; half < 2; half++) {
                int r = r0 + wm*32 + mt*16 + g + half*8;
                int b_ = r >> 10, n = r & 1023;
                float v0 = acc[mt][nt][2*half]   + b0v;
                float v1 = acc[mt][nt][2*half+1] + b1v;
                int zz = b_*NHEADS + h;
                if (z < 2) {
                    size_t base = (((size_t)zz)*NN + n)*DD + dd;
                    *(float2*)(outf + base) = make_float2(v0, v1);
                    uint32_t hw, lw;
                    split2(v0, v1, hw, lw);
                    *(uint32_t*)(ghi + base) = hw;
                    *(uint32_t*)(glo + base) = lw;
                } else {
                    // V^T layout (z, d, n)
                    uint32_t hw, lw;
                    split2(v0, v1, hw, lw);
                    __nv_bfloat162 hp = *(__nv_bfloat162*)&hw;
                    __nv_bfloat162 lp = *(__nv_bfloat162*)&lw;
                    size_t b0i = ((size_t)zz*DD + dd)*NN + n;
                    size_t b1i = ((size_t)zz*DD + dd + 1)*NN + n;
                    g_vthi[b0i] = hp.x; g_vtlo[b0i] = lp.x;
                    g_vthi[b1i] = hp.y; g_vtlo[b1i] = lp.y;
                }
            }
        }
    }
}

// ---------------------------------------------------------------------------
// K2: scores = Q K^T / 8, K=64 resident, pure bf16 mma.
// ---------------------------------------------------------------------------
__global__ __launch_bounds__(256) void k_scores(float* __restrict__ scores) {
    extern __shared__ __nv_bfloat16 sm2[];
    __nv_bfloat16 (*Qhi)[72] = (__nv_bfloat16(*)[72])sm2;
    __nv_bfloat16 (*Qlo)[72] = Qhi + 128;
    __nv_bfloat16 (*Khi)[72] = Qlo + 128;
    __nv_bfloat16 (*Klo)[72] = Khi + 128;

    int z = blockIdx.z;
    float* S = scores + (size_t)z*NN*NN;
    int tid = threadIdx.x, lane = tid & 31, w = tid >> 5;
    int wm = w & 3, wn = w >> 2;
    int n0 = blockIdx.y * 128, m0 = blockIdx.x * 128;

    // load Q/K tiles (K=64): thread -> row tid>>1, 4 uint4 at (tid&1)*32
    {
        int lr = tid >> 1, c0 = (tid & 1) * 32;
        size_t qi = ((size_t)z*NN + n0 + lr)*DD + c0;
        size_t ki = ((size_t)z*NN + m0 + lr)*DD + c0;
        #pragma unroll
        for (int c = 0; c < 4; c++) {
            *(uint4*)&Qhi[lr][c0 + c*8] = *(const uint4*)&g_qhi[qi + c*8];
            *(uint4*)&Qlo[lr][c0 + c*8] = *(const uint4*)&g_qlo[qi + c*8];
            *(uint4*)&Khi[lr][c0 + c*8] = *(const uint4*)&g_khi[ki + c*8];
            *(uint4*)&Klo[lr][c0 + c*8] = *(const uint4*)&g_klo[ki + c*8];
        }
    }
    __syncthreads();

    float acc[2][8][4];
    #pragma unroll
    for (int i = 0; i < 2; i++)
        #pragma unroll
        for (int j = 0; j < 8; j++)
            #pragma unroll
            for (int c = 0; c < 4; c++) acc[i][j][c] = 0.f;

    int arow = wm*32 + (lane & 15);
    int brow = wn*64 + (lane & 7) + ((lane >> 4) << 3);
    int bcol8 = ((lane >> 3) & 1) * 8;
    int acol8 = (lane >> 4) * 8;

    #pragma unroll
    for (int k16 = 0; k16 < DD; k16 += 16) {
        uint32_t ahi[2][4], alo2[2][4];
        #pragma unroll
        for (int mt = 0; mt < 2; mt++) {
            ldsm4(ahi[mt],  &Qhi[arow + mt*16][k16 + acol8]);
            ldsm4(alo2[mt], &Qlo[arow + mt*16][k16 + acol8]);
        }
        #pragma unroll
        for (int p = 0; p < 4; p++) {
            uint32_t bh[4], blw[4];
            ldsm4(bh,  &Khi[brow + p*16][k16 + bcol8]);
            ldsm4(blw, &Klo[brow + p*16][k16 + bcol8]);
            #pragma unroll
            for (int mt = 0; mt < 2; mt++) {
                mma16816(acc[mt][2*p],   ahi[mt],  bh);
                mma16816(acc[mt][2*p],   ahi[mt],  blw);
                mma16816(acc[mt][2*p],   alo2[mt], bh);
                mma16816(acc[mt][2*p+1], ahi[mt],  bh+2);
                mma16816(acc[mt][2*p+1], ahi[mt],  blw+2);
                mma16816(acc[mt][2*p+1], alo2[mt], bh+2);
            }
        }
    }

    int g = lane >> 2, t2 = (lane & 3) * 2;
    #pragma unroll
    for (int mt = 0; mt < 2; mt++) {
        int r = n0 + wm*32 + mt*16 + g;
        #pragma unroll
        for (int nt = 0; nt < 8; nt++) {
            int col = m0 + wn*64 + nt*8 + t2;
            *(float2*)(S + (size_t)r*NN + col) =
                make_float2(acc[mt][nt][0]*0.125f, acc[mt][nt][1]*0.125f);
            *(float2*)(S + (size_t)(r+8)*NN + col) =
                make_float2(acc[mt][nt][2]*0.125f, acc[mt][nt][3]*0.125f);
        }
    }
}

// ---------------------------------------------------------------------------
// K3: per-row softmax stats
// ---------------------------------------------------------------------------
__global__ void k_stats(const float* __restrict__ scores) {
    int gwarp = (blockIdx.x * blockDim.x + threadIdx.x) >> 5;
    int lane  = threadIdx.x & 31;
    if (gwarp >= BH*NN) return;
    int b = gwarp / (NHEADS*NN);
    int n = gwarp & (NN-1);
    int padd = g_padd[b];
    if (n >= padd) {
        if (lane == 0) { g_rowmax[gwarp] = 0.f; g_rowsum[gwarp] = 1.f; }
        return;
    }
    const float* row = scores + (size_t)gwarp*NN;
    float vmax = -1e30f, vsum = 0.f;
    for (int m4 = lane*4; m4 < NN; m4 += 128) {
        if (m4 >= padd) break;
        float4 s4 = *(const float4*)(row + m4);
        float sv[4] = {s4.x, s4.y, s4.z, s4.w};
        #pragma unroll
        for (int j = 0; j < 4; j++) {
            if (m4 + j >= padd) break;
            float s = sv[j];
            if (s > vmax) { vsum = vsum*__expf(vmax - s) + 1.f; vmax = s; }
            else            vsum += __expf(s - vmax);
        }
    }
    #pragma unroll
    for (int o = 16; o > 0; o >>= 1) {
        float omax = __shfl_xor_sync(0xffffffffu, vmax, o);
        float osum = __shfl_xor_sync(0xffffffffu, vsum, o);
        float m2 = fmaxf(vmax, omax);
        vsum = vsum*__expf(vmax - m2) + osum*__expf(omax - m2);
        vmax = m2;
    }
    if (lane == 0) { g_rowmax[gwarp] = vmax; g_rowsum[gwarp] = vsum; }
}

// ---------------------------------------------------------------------------
// K4: zero attention_values
// ---------------------------------------------------------------------------
__global__ void k_zero(float* __restrict__ av) {
    av[(size_t)blockIdx.x*1024 + threadIdx.x] = 0.f;
}

// ---------------------------------------------------------------------------
// K5: context = P @ V (tensor cores, bf16 hi/lo 3-product) + column sums.
// ---------------------------------------------------------------------------
__global__ __launch_bounds__(256) void k_ctx(const float* __restrict__ scores,
        float* __restrict__ ctx, float* __restrict__ av) {
    extern __shared__ __nv_bfloat16 smc[];
    __nv_bfloat16 (*Phi)[136] = (__nv_bfloat16(*)[136])smc;          // [n][m]
    __nv_bfloat16 (*Plo)[136] = Phi + 128;
    __nv_bfloat16 (*Vhi)[136] = Plo + 128;                           // [d][m]
    __nv_bfloat16 (*Vlo)[136] = Vhi + 64;
    float* smax = (float*)(Vlo + 64);
    float* sinv = smax + 128;

    int z = blockIdx.y, b = z >> 4;
    int padd = g_padd[b];
    int n0 = blockIdx.x * 128;
    int tid = threadIdx.x, lane = tid & 31, w = tid >> 5;
    int wm = w & 3, wn = w >> 2;

    if (n0 >= padd) {
        float4 zz = make_float4(0.f,0.f,0.f,0.f);
        for (int e = 0; e < 8; e++) {
            int l = e*256 + tid;
            *(float4*)(ctx + ((size_t)z*NN + n0)*DD + l*4) = zz;
        }
        return;
    }

    const float* S = scores + (size_t)z*NN*NN;

    if (tid < 128) {
        int row = z*NN + n0 + tid;
        smax[tid] = g_rowmax[row];
        sinv[tid] = 1.f / g_rowsum[row];
    }
    __syncthreads();

    float acc[2][4][4];
    #pragma unroll
    for (int i = 0; i < 2; i++)
        #pragma unroll
        for (int j = 0; j < 4; j++)
            #pragma unroll
            for (int c = 0; c < 4; c++) acc[i][j][c] = 0.f;

    int arow = wm*32 + (lane & 15);
    int brow = wn*32 + (lane & 7) + ((lane >> 4) << 3);
    int bcol8 = ((lane >> 3) & 1) * 8;
    int acol8 = (lane >> 4) * 8;

    for (int m0 = 0; m0 < padd; m0 += 128) {
        // build P tile -> bf16 hi/lo
        #pragma unroll
        for (int e = 0; e < 16; e++) {
            int l = e*256 + tid;
            int n = l >> 5, m4 = (l & 31) * 4;
            float4 s4 = *(const float4*)(S + (size_t)(n0+n)*NN + m0 + m4);
            float4 p4 = make_float4(0.f, 0.f, 0.f, 0.f);
            if (n0 + n < padd) {
                float mx = smax[n], iv = sinv[n];
                int mg = m0 + m4;
                if (mg + 0 < padd) p4.x = __expf(s4.x - mx) * iv;
                if (mg + 1 < padd) p4.y = __expf(s4.y - mx) * iv;
                if (mg + 2 < padd) p4.z = __expf(s4.z - mx) * iv;
                if (mg + 3 < padd) p4.w = __expf(s4.w - mx) * iv;
            }
            uint2 hw, lw;
            split2(p4.x, p4.y, hw.x, lw.x);
            split2(p4.z, p4.w, hw.y, lw.y);
            *(uint2*)&Phi[n][m4] = hw;
            *(uint2*)&Plo[n][m4] = lw;
        }
        // load V^T tiles: rows d (64), cols m (128)
        {
            int dr = tid >> 2;                  // 0..63
            int c0 = (tid & 3) * 8;             // 4 segs of 8, stride 32
            size_t vi = ((size_t)z*DD + dr)*NN + m0 + c0;
            #pragma unroll
            for (int c = 0; c < 4; c++) {
                *(uint4*)&Vhi[dr][c0 + c*32] = *(const uint4*)&g_vthi[vi + c*32];
                *(uint4*)&Vlo[dr][c0 + c*32] = *(const uint4*)&g_vtlo[vi + c*32];
            }
        }
        __syncthreads();

        // mma: acc[n][d] += P[n][m] * V^T[d][m]
        #pragma unroll
        for (int k16 = 0; k16 < 128; k16 += 16) {
            uint32_t ahi[2][4], alo2[2][4];
            #pragma unroll
            for (int mt = 0; mt < 2; mt++) {
                ldsm4(ahi[mt],  &Phi[arow + mt*16][k16 + acol8]);
                ldsm4(alo2[mt], &Plo[arow + mt*16][k16 + acol8]);
            }
            #pragma unroll
            for (int p = 0; p < 2; p++) {
                uint32_t bh[4], blw[4];
                ldsm4(bh,  &Vhi[brow + p*16][k16 + bcol8]);
                ldsm4(blw, &Vlo[brow + p*16][k16 + bcol8]);
                #pragma unroll
                for (int mt = 0; mt < 2; mt++) {
                    mma16816(acc[mt][2*p],   ahi[mt],  bh);
                    mma16816(acc[mt][2*p],   ahi[mt],  blw);
                    mma16816(acc[mt][2*p],   alo2[mt], bh);
                    mma16816(acc[mt][2*p+1], ahi[mt],  bh+2);
                    mma16816(acc[mt][2*p+1], ahi[mt],  blw+2);
                    mma16816(acc[mt][2*p+1], alo2[mt], bh+2);
                }
            }
        }

        // column sums -> attention_values (exact: hi+lo)
        if (tid < 128) {
            float s = 0.f;
            #pragma unroll 4
            for (int n = 0; n < 128; n++)
                s += __bfloat162float(Phi[n][tid]) + __bfloat162float(Plo[n][tid]);
            if (s != 0.f) atomicAdd(av + (size_t)z*NN + m0 + tid, s);
        }
        __syncthreads();
    }

    int g = lane >> 2, t2 = (lane & 3) * 2;
    #pragma unroll
    for (int mt = 0; mt < 2; mt++) {
        #pragma unroll
        for (int nt = 0; nt < 4; nt++) {
            int col = wn*32 + nt*8 + t2;
            int r = n0 + wm*32 + mt*16 + g;
            *(float2*)(ctx + ((size_t)z*NN + r)*DD + col) =
                make_float2(acc[mt][nt][0], acc[mt][nt][1]);
            *(float2*)(ctx + ((size_t)z*NN + r + 8)*DD + col) =
                make_float2(acc[mt][nt][2], acc[mt][nt][3]);
        }
    }
}

// ---------------------------------------------------------------------------
extern "C" void kernel_launch(void* const* d_in, const int* in_sizes, int n_in,
                              void* d_out, int out_size) {
    const float* hs = (const float*)d_in[0];
    const int*  pad = (const int*)  d_in[1];
    const float* Wq = (const float*)d_in[2];
    const float* bq = (const float*)d_in[3];
    const float* Wk = (const float*)d_in[4];
    const float* bk = (const float*)d_in[5];
    const float* Wv = (const float*)d_in[6];
    const float* bv = (const float*)d_in[7];

    float* out    = (float*)d_out;
    float* av     = out;
    float* outk   = av + (size_t)BH*NN;
    float* outq   = outk + (size_t)BH*NN*DD;
    float* ctx    = outq + (size_t)BH*NN*DD;
    float* scores = ctx  + (size_t)BH*NN*DD;

    // resolve scratch symbol addresses (host-side, not stream ops)
    static __nv_bfloat16 *xhi=nullptr,*xlo=nullptr,*whi=nullptr,*wlo=nullptr;
    if (!xhi) {
        cudaGetSymbolAddress((void**)&xhi, g_xhi);
        cudaGetSymbolAddress((void**)&xlo, g_xlo);
        cudaGetSymbolAddress((void**)&whi, g_whi);
        cudaGetSymbolAddress((void**)&wlo, g_wlo);
    }

    const int SC_SMEM  = 4*128*72*2;                          // 73728
    const int CTX_SMEM = (2*128*136 + 2*64*136)*2 + 256*4;    // 105472
    cudaFuncSetAttribute(k_scores, cudaFuncAttributeMaxDynamicSharedMemorySize, SC_SMEM);
    cudaFuncSetAttribute(k_ctx,    cudaFuncAttributeMaxDynamicSharedMemorySize, CTX_SMEM);

    k_padd  <<<BB, 256>>>(pad);
    k_conv  <<<(ROWS*HH/4)/256, 256>>>(hs, xhi, xlo);
    k_conv  <<<(HH*HH/4)/256, 256>>>(Wq, whi,            wlo);
    k_conv  <<<(HH*HH/4)/256, 256>>>(Wk, whi + HH*HH,    wlo + HH*HH);
    k_conv  <<<(HH*HH/4)/256, 256>>>(Wv, whi + 2*HH*HH,  wlo + 2*HH*HH);
    k_qkv   <<<dim3(HH/128, ROWS/128, 3), 256>>>(bq, bk, bv, outq, outk);
    k_scores<<<dim3(NN/128, NN/128, BH), 256, SC_SMEM>>>(scores);
    k_stats <<<(BH*NN*32)/256, 256>>>(scores);
    k_zero  <<<BH, 1024>>>(av);
    k_ctx   <<<dim3(NN/128, BH), 256, CTX_SMEM>>>(scores, ctx, av);
}